// round 7
// baseline (speedup 1.0000x reference)
#include <cuda_runtime.h>
#include <cuda_bf16.h>
#include <mma.h>
#include <math.h>
#include <stdint.h>

using namespace nvcuda;

// ---------------- problem constants ----------------
#define DIM   256
#define H1N   128
#define H2N   64
#define TM    64       // rows per CTA tile
#define KC    32       // K-chunk for GEMM1
#define NT    256
#define NGRAPH 2048
#define PROWS 512

// ---------------- smem layout (bytes) ----------------
// XB0/XB1 : 64 x 36 f32 = 9216 each      -> [0, 18432)
// W1B     : 32 x 132 f32 = 16896         -> [18432, 35328)
// H1      : 64 x 132 f32 = 33792  (aliases [0, 35328) after GEMM1)
// W2B     : 128 x 68 f32 = 34816         -> [35328, 70144)
// H2      : 64 x 68 f32 = 17408   (aliases W2B after GEMM2)
// BIAS    : 256 f32 = 1024               -> [70144, 71168)
#define OFF_XB0  0
#define OFF_XB1  9216
#define OFF_W1B  18432
#define OFF_H1   0
#define OFF_W2   35328
#define OFF_H2   35328
#define OFF_BIAS 70144
#define SMEM_TOTAL 71168

// ---------------- device scratch ----------------
__device__ float g_ebuf[600064];
__device__ float g_segsum[4096];

// ---------------- cp.async helpers ----------------
static __device__ __forceinline__ uint32_t s2u(const void* p) {
    uint32_t a;
    asm("{ .reg .u64 t; cvta.to.shared.u64 t, %1; cvt.u32.u64 %0, t; }" : "=r"(a) : "l"(p));
    return a;
}
#define CP16(dst, src) \
    asm volatile("cp.async.cg.shared.global [%0], [%1], 16;" :: "r"(dst), "l"(src))
#define CP_COMMIT() asm volatile("cp.async.commit_group;" ::: "memory")
#define CP_WAIT(n)  asm volatile("cp.async.wait_group %0;" :: "n"(n) : "memory")

// ---------------- init: zero output + segment sums ----------------
__global__ void init_kernel(float* __restrict__ out, int n) {
    int i = blockIdx.x * blockDim.x + threadIdx.x;
    if (i < n) out[i] = 0.0f;
    if (i < 4096) g_segsum[i] = 0.0f;
}

// ---------------- fused MLP: cp.async pipelined tf32 wmma, 3 CTAs/SM ----------------
// 256 threads, 8 warps (2 row-tiles x 4 col-tiles of 32x32), 64 rows/CTA.
__global__ void __launch_bounds__(NT, 3)
mlp_kernel(const float* __restrict__ Xn, const int* __restrict__ idxn,
           const float* __restrict__ Wn1, const float* __restrict__ bn1,
           const float* __restrict__ Wn2, const float* __restrict__ bn2,
           const float* __restrict__ wn3, const float* __restrict__ bn3,
           const float* __restrict__ Xe, const int* __restrict__ idxe,
           const float* __restrict__ We1, const float* __restrict__ be1,
           const float* __restrict__ We2, const float* __restrict__ be2,
           const float* __restrict__ we3, const float* __restrict__ be3,
           int nTilesNodes, int nNodes, int nEdges) {
    extern __shared__ char smem[];
    float* W1B  = (float*)(smem + OFF_W1B);
    float* H1   = (float*)(smem + OFF_H1);
    float* W2B  = (float*)(smem + OFF_W2);
    float* H2   = (float*)(smem + OFF_H2);
    float* BIAS = (float*)(smem + OFF_BIAS);
    const uint32_t sb = s2u(smem);

    const int bid = blockIdx.x;
    const bool isNode = bid < nTilesNodes;
    const float* X   = isNode ? Xn : Xe;
    const int*   idx = isNode ? idxn : idxe;
    const float* W1  = isNode ? Wn1 : We1;
    const float* W2  = isNode ? Wn2 : We2;
    const float* b1  = isNode ? bn1 : be1;
    const float* b2  = isNode ? bn2 : be2;
    const float* w3  = isNode ? wn3 : we3;
    const float* b3  = isNode ? bn3 : be3;
    const int nRows  = isNode ? nNodes : nEdges;
    const int eOff   = isNode ? 0 : 200000;
    const int sOff   = isNode ? 0 : NGRAPH;
    const int rowBase = (isNode ? bid : bid - nTilesNodes) * TM;

    const int t = threadIdx.x;
    const int wid = t >> 5;
    const int wm = wid & 1;    // 0..1 : 32-row tile
    const int wn = wid >> 1;   // 0..3 : 32-col tile

    if (t < H1N) BIAS[t] = b1[t];
    if (t < H2N) { BIAS[128 + t] = b2[t]; BIAS[192 + t] = w3[t]; }

    // ---- prologue: X chunk 0 (group), W2 (group) ----
    {
#pragma unroll
        for (int i = 0; i < 2; i++) {           // 512 float4: X[64 x 32]
            int e = t + i * NT;
            int r = e >> 3, kk = (e & 7) * 4;
            int gr = rowBase + r; if (gr >= nRows) gr = nRows - 1;
            CP16(sb + OFF_XB0 + (r * 36 + kk) * 4, &X[(size_t)gr * DIM + kk]);
        }
        CP_COMMIT();
#pragma unroll
        for (int i = 0; i < 8; i++) {           // 2048 float4: W2[128 x 64]
            int e = t + i * NT;
            int r = e >> 4, cc = (e & 15) * 4;
            CP16(sb + OFF_W2 + (r * 68 + cc) * 4, &W2[r * H2N + cc]);
        }
        CP_COMMIT();
    }

    typedef wmma::fragment<wmma::matrix_a, 16, 16, 8, wmma::precision::tf32, wmma::row_major> FragA;
    typedef wmma::fragment<wmma::matrix_b, 16, 16, 8, wmma::precision::tf32, wmma::row_major> FragB;
    typedef wmma::fragment<wmma::accumulator, 16, 16, 8, float> FragC;

    // ================= GEMM1: [64 x 256] @ [256 x 128] =================
    FragC acc[2][2];
#pragma unroll
    for (int mi = 0; mi < 2; mi++)
#pragma unroll
        for (int ni = 0; ni < 2; ni++) wmma::fill_fragment(acc[mi][ni], 0.0f);

    const int NCHUNK = DIM / KC;  // 8
    for (int c = 0; c < NCHUNK; c++) {
        // issue W1 chunk c (single buffer — free since post-mma barrier of c-1)
        {
            const int k0 = c * KC;
#pragma unroll
            for (int i = 0; i < 4; i++) {       // 1024 float4: W1[32 x 128]
                int e = t + i * NT;
                int r = e >> 5, cc = (e & 31) * 4;
                CP16(sb + OFF_W1B + (r * 132 + cc) * 4, &W1[(k0 + r) * H1N + cc]);
            }
            CP_COMMIT();
        }
        // issue X chunk c+1 (double buffer)
        if (c + 1 < NCHUNK) {
            const int k0 = (c + 1) * KC;
            const uint32_t xb = ((c + 1) & 1) ? OFF_XB1 : OFF_XB0;
#pragma unroll
            for (int i = 0; i < 2; i++) {
                int e = t + i * NT;
                int r = e >> 3, kk = (e & 7) * 4;
                int gr = rowBase + r; if (gr >= nRows) gr = nRows - 1;
                CP16(sb + xb + (r * 36 + kk) * 4, &X[(size_t)gr * DIM + k0 + kk]);
            }
            CP_COMMIT();
            CP_WAIT(1);    // X(c), W1(c) [and W2] resident; X(c+1) in flight
        } else {
            CP_WAIT(0);
        }
        __syncthreads();

        float* XB = (float*)(smem + ((c & 1) ? OFF_XB1 : OFF_XB0));
#pragma unroll
        for (int ks = 0; ks < KC / 8; ks++) {
            const int kb = ks * 8;
            FragA a[2];
            FragB b[2];
#pragma unroll
            for (int mi = 0; mi < 2; mi++)
                wmma::load_matrix_sync(a[mi], XB + (wm * 32 + mi * 16) * 36 + kb, 36);
#pragma unroll
            for (int ni = 0; ni < 2; ni++)
                wmma::load_matrix_sync(b[ni], W1B + kb * 132 + wn * 32 + ni * 16, 132);
#pragma unroll
            for (int mi = 0; mi < 2; mi++)
#pragma unroll
                for (int ni = 0; ni < 2; ni++)
                    wmma::mma_sync(acc[mi][ni], a[mi], b[ni], acc[mi][ni]);
        }
        __syncthreads();   // all warps done with W1B / old X buffer
    }

    // ---- epilogue 1: H1 = relu(acc + b1)   (H1 aliases X/W1 buffers) ----
#pragma unroll
    for (int mi = 0; mi < 2; mi++)
#pragma unroll
        for (int ni = 0; ni < 2; ni++)
            wmma::store_matrix_sync(H1 + (wm * 32 + mi * 16) * 132 + wn * 32 + ni * 16,
                                    acc[mi][ni], 132, wmma::mem_row_major);
    __syncthreads();
#pragma unroll
    for (int i = 0; i < 8; i++) {
        int e = t + i * NT;
        int r = e >> 5, cc = (e & 31) * 4;
        float4 v = *(float4*)&H1[r * 132 + cc];
        v.x = fmaxf(v.x + BIAS[cc + 0], 0.f);
        v.y = fmaxf(v.y + BIAS[cc + 1], 0.f);
        v.z = fmaxf(v.z + BIAS[cc + 2], 0.f);
        v.w = fmaxf(v.w + BIAS[cc + 3], 0.f);
        *(float4*)&H1[r * 132 + cc] = v;
    }
    __syncthreads();

    // ================= GEMM2: [64 x 128] @ [128 x 64] =================
    // warp tile: 32 rows x 16 cols  (wm2 = wid&1, wn2 = wid>>1)
    const int wm2 = wid & 1;
    const int wn2 = wid >> 1;
    FragC acc2[2];
#pragma unroll
    for (int mi = 0; mi < 2; mi++) wmma::fill_fragment(acc2[mi], 0.0f);
#pragma unroll
    for (int ks = 0; ks < H1N / 8; ks++) {
        const int kb = ks * 8;
        FragA a[2];
        FragB b;
#pragma unroll
        for (int mi = 0; mi < 2; mi++)
            wmma::load_matrix_sync(a[mi], H1 + (wm2 * 32 + mi * 16) * 132 + kb, 132);
        wmma::load_matrix_sync(b, W2B + kb * 68 + wn2 * 16, 68);
#pragma unroll
        for (int mi = 0; mi < 2; mi++)
            wmma::mma_sync(acc2[mi], a[mi], b, acc2[mi]);
    }
    __syncthreads();   // W2B reads done before H2 overwrites it
#pragma unroll
    for (int mi = 0; mi < 2; mi++)
        wmma::store_matrix_sync(H2 + (wm2 * 32 + mi * 16) * 68 + wn2 * 16,
                                acc2[mi], 68, wmma::mem_row_major);
    __syncthreads();

    // ================= layer 3 + exp + segment sum (4 threads/row) =================
    {
        const int row = t >> 2;        // 0..63
        const int q   = t & 3;         // 0..3 -> 16 cols each
        float s = 0.0f;
#pragma unroll
        for (int j = 0; j < 16; j++) {
            int c = q * 16 + j;
            float v = fmaxf(H2[row * 68 + c] + BIAS[128 + c], 0.0f);
            s = fmaf(v, BIAS[192 + c], s);
        }
        s += __shfl_xor_sync(0xFFFFFFFF, s, 1);
        s += __shfl_xor_sync(0xFFFFFFFF, s, 2);
        if (q == 0) {
            int gr = rowBase + row;
            if (gr < nRows) {
                float e = __expf(s + b3[0]);   // logits O(1): no max-subtraction needed
                g_ebuf[eOff + gr] = e;
                atomicAdd(&g_segsum[sOff + idx[gr]], e);
            }
        }
    }
}

// ---------------- pool: att-weighted segment sum (sorted indices) ----------------
__global__ void __launch_bounds__(NT)
pool_kernel(const float* __restrict__ Xn, const int* __restrict__ idxn,
            const float* __restrict__ Xe, const int* __restrict__ idxe,
            float* __restrict__ out, int nbNodes, int nNodes, int nEdges) {
    __shared__ float rw[PROWS];
    __shared__ int   sg[PROWS];

    const int bid = blockIdx.x;
    const bool isNode = bid < nbNodes;
    const float* X   = isNode ? Xn : Xe;
    const int*   idx = isNode ? idxn : idxe;
    const int nRows  = isNode ? nNodes : nEdges;
    const int eOff   = isNode ? 0 : 200000;
    const int sOff   = isNode ? 0 : NGRAPH;
    float* outH      = isNode ? out : out + NGRAPH * DIM;
    const int base   = (isNode ? bid : bid - nbNodes) * PROWS;
    const int rows   = min(PROWS, nRows - base);

    const int t = threadIdx.x;
    for (int i = t; i < rows; i += NT) {
        int g = base + i;
        int s = idx[g];
        sg[i] = s;
        rw[i] = g_ebuf[eOff + g] / g_segsum[sOff + s];
    }
    __syncthreads();

    const int grp = t >> 6;
    const int col = (t & 63) * 4;
    const int r0 = grp * 128;
    if (r0 < rows) {
        const int rend = min(r0 + 128, rows);
        float4 acc = make_float4(0.f, 0.f, 0.f, 0.f);
        int cur = sg[r0];
        for (int i = r0; i < rend; i++) {
            float4 x = *(const float4*)&X[(size_t)(base + i) * DIM + col];
            int s = sg[i];
            if (s != cur) {
                size_t o = (size_t)cur * DIM + col;
                atomicAdd(&outH[o + 0], acc.x);
                atomicAdd(&outH[o + 1], acc.y);
                atomicAdd(&outH[o + 2], acc.z);
                atomicAdd(&outH[o + 3], acc.w);
                acc = make_float4(0.f, 0.f, 0.f, 0.f);
                cur = s;
            }
            float w = rw[i];
            acc.x = fmaf(w, x.x, acc.x);
            acc.y = fmaf(w, x.y, acc.y);
            acc.z = fmaf(w, x.z, acc.z);
            acc.w = fmaf(w, x.w, acc.w);
        }
        size_t o = (size_t)cur * DIM + col;
        atomicAdd(&outH[o + 0], acc.x);
        atomicAdd(&outH[o + 1], acc.y);
        atomicAdd(&outH[o + 2], acc.z);
        atomicAdd(&outH[o + 3], acc.w);
    }
}

// ---------------- launch ----------------
extern "C" void kernel_launch(void* const* d_in, const int* in_sizes, int n_in,
                              void* d_out, int out_size) {
    const float* emb_nodes  = (const float*)d_in[0];
    const float* emb_edges  = (const float*)d_in[1];
    const int*   node_index = (const int*)d_in[2];
    const int*   edge_index = (const int*)d_in[3];
    const float* Wn1 = (const float*)d_in[4];
    const float* bn1 = (const float*)d_in[5];
    const float* Wn2 = (const float*)d_in[6];
    const float* bn2 = (const float*)d_in[7];
    const float* Wn3 = (const float*)d_in[8];
    const float* bn3 = (const float*)d_in[9];
    const float* We1 = (const float*)d_in[10];
    const float* be1 = (const float*)d_in[11];
    const float* We2 = (const float*)d_in[12];
    const float* be2 = (const float*)d_in[13];
    const float* We3 = (const float*)d_in[14];
    const float* be3 = (const float*)d_in[15];

    const int n_nodes = in_sizes[0] / DIM;   // 200000
    const int n_edges = in_sizes[1] / DIM;   // 400000
    float* out = (float*)d_out;

    init_kernel<<<(out_size + NT - 1) / NT, NT>>>(out, out_size);

    cudaFuncSetAttribute(mlp_kernel, cudaFuncAttributeMaxDynamicSharedMemorySize, SMEM_TOTAL);

    const int tn = (n_nodes + TM - 1) / TM;   // 3125
    const int te = (n_edges + TM - 1) / TM;   // 6250
    mlp_kernel<<<tn + te, NT, SMEM_TOTAL>>>(
        emb_nodes, node_index, Wn1, bn1, Wn2, bn2, Wn3, bn3,
        emb_edges, edge_index, We1, be1, We2, be2, We3, be3,
        tn, n_nodes, n_edges);

    const int pn = (n_nodes + PROWS - 1) / PROWS;
    const int pe = (n_edges + PROWS - 1) / PROWS;
    pool_kernel<<<pn + pe, NT>>>(
        emb_nodes, node_index, emb_edges, edge_index, out, pn, n_nodes, n_edges);
}

// round 8
// speedup vs baseline: 1.0475x; 1.0475x over previous
#include <cuda_runtime.h>
#include <cuda_bf16.h>
#include <mma.h>
#include <math.h>
#include <stdint.h>

using namespace nvcuda;

// ---------------- problem constants ----------------
#define DIM   256
#define H1N   128
#define H2N   64
#define TM    128      // rows per tile
#define KC    16       // K-chunk for GEMM1
#define NCH   16       // chunks = DIM/KC
#define NT    256
#define NGRAPH 2048
#define PROWS 512
#define CTA_NODE 49
#define CTA_TOTAL 148

// ---------------- smem layout (bytes) ----------------
// W1S : 256 x 132 f32 = 135168      [0, 135168)
// W2S : 128 x 68 f32  = 34816      [135168, 169984)
// XB  : 4 x (128 x 20 f32 = 10240) [169984, 210944)
// H1q : 128 x 36 f32 = 18432   (aliases XB)
// H2  : 128 x 68 f32 = 34816   (aliases XB)
// BIAS: 256 f32                    [210944, 211968)
#define OFF_W1  0
#define OFF_W2  135168
#define OFF_XB  169984
#define XBUF(i) (OFF_XB + (i) * 10240)
#define OFF_H1  OFF_XB
#define OFF_H2  OFF_XB
#define OFF_BIAS 210944
#define SMEM_TOTAL 211968

// ---------------- device scratch ----------------
__device__ float g_ebuf[600064];
__device__ float g_segsum[4096];

// ---------------- cp.async helpers ----------------
static __device__ __forceinline__ uint32_t s2u(const void* p) {
    uint32_t a;
    asm("{ .reg .u64 t; cvta.to.shared.u64 t, %1; cvt.u32.u64 %0, t; }" : "=r"(a) : "l"(p));
    return a;
}
#define CP16(dst, src) \
    asm volatile("cp.async.cg.shared.global [%0], [%1], 16;" :: "r"(dst), "l"(src))
#define CP_COMMIT() asm volatile("cp.async.commit_group;" ::: "memory")
#define CP_WAIT(n)  asm volatile("cp.async.wait_group %0;" :: "n"(n) : "memory")

// ---------------- init: zero output + segment sums ----------------
__global__ void init_kernel(float* __restrict__ out, int n) {
    int i = blockIdx.x * blockDim.x + threadIdx.x;
    if (i < n) out[i] = 0.0f;
    if (i < 4096) g_segsum[i] = 0.0f;
}

// ---------------- persistent fused MLP: resident weights + X ring ----------------
// 148 CTAs (1/SM), 256 threads, 8 warps (4 row x 2 col), 128 rows/tile.
__global__ void __launch_bounds__(NT, 1)
mlp_kernel(const float* __restrict__ Xn, const int* __restrict__ idxn,
           const float* __restrict__ Wn1, const float* __restrict__ bn1,
           const float* __restrict__ Wn2, const float* __restrict__ bn2,
           const float* __restrict__ wn3, const float* __restrict__ bn3,
           const float* __restrict__ Xe, const int* __restrict__ idxe,
           const float* __restrict__ We1, const float* __restrict__ be1,
           const float* __restrict__ We2, const float* __restrict__ be2,
           const float* __restrict__ we3, const float* __restrict__ be3,
           int nNodes, int nEdges) {
    extern __shared__ char smem[];
    float* W1S  = (float*)(smem + OFF_W1);
    float* W2S  = (float*)(smem + OFF_W2);
    float* H1   = (float*)(smem + OFF_H1);
    float* H2   = (float*)(smem + OFF_H2);
    float* BIAS = (float*)(smem + OFF_BIAS);
    const uint32_t sb = s2u(smem);

    const int bid = blockIdx.x;
    const bool isNode = bid < CTA_NODE;
    const float* X   = isNode ? Xn : Xe;
    const int*   idx = isNode ? idxn : idxe;
    const float* W1  = isNode ? Wn1 : We1;
    const float* W2  = isNode ? Wn2 : We2;
    const float* b1  = isNode ? bn1 : be1;
    const float* b2  = isNode ? bn2 : be2;
    const float* w3  = isNode ? wn3 : we3;
    const float* b3  = isNode ? bn3 : be3;
    const int nRows  = isNode ? nNodes : nEdges;
    const int eOff   = isNode ? 0 : 200000;
    const int sOff   = isNode ? 0 : NGRAPH;
    const int nTiles = (nRows + TM - 1) / TM;
    const int myCta  = isNode ? bid : bid - CTA_NODE;
    const int ctaCnt = isNode ? CTA_NODE : (CTA_TOTAL - CTA_NODE);

    const int t = threadIdx.x;
    const int wid = t >> 5;
    const int wm = wid >> 1;   // 0..3 : 32-row tile
    const int wn = wid & 1;    // 0..1 : col group

    // ---- resident weights: one cp.async group ----
#pragma unroll
    for (int i = 0; i < 32; i++) {              // W1 [256 x 128] -> stride 132
        int e = t + i * NT;
        int r = e >> 5, cc = (e & 31) * 4;
        CP16(sb + OFF_W1 + (r * 132 + cc) * 4, &W1[r * H1N + cc]);
    }
#pragma unroll
    for (int i = 0; i < 8; i++) {               // W2 [128 x 64] -> stride 68
        int e = t + i * NT;
        int r = e >> 4, cc = (e & 15) * 4;
        CP16(sb + OFF_W2 + (r * 68 + cc) * 4, &W2[r * H2N + cc]);
    }
    CP_COMMIT();

    if (t < H1N) BIAS[t] = b1[t];
    if (t < H2N) { BIAS[128 + t] = b2[t]; BIAS[192 + t] = w3[t]; }
    const float b3v = b3[0];

    typedef wmma::fragment<wmma::matrix_a, 16, 16, 8, wmma::precision::tf32, wmma::row_major> FragA;
    typedef wmma::fragment<wmma::matrix_b, 16, 16, 8, wmma::precision::tf32, wmma::row_major> FragB;
    typedef wmma::fragment<wmma::accumulator, 16, 16, 8, float> FragC;

    for (int tile = myCta; tile < nTiles; tile += ctaCnt) {
        const int rowBase = tile * TM;

        // ---- prologue: issue X chunks 0..2 ----
#pragma unroll
        for (int c0 = 0; c0 < 3; c0++) {
            const int k0 = c0 * KC;
#pragma unroll
            for (int i = 0; i < 2; i++) {       // 512 float4 per chunk
                int e = t + i * NT;
                int r = e >> 2, kk = (e & 3) * 4;
                int gr = rowBase + r; if (gr >= nRows) gr = nRows - 1;
                CP16(sb + XBUF(c0) + (r * 20 + kk) * 4, &X[(size_t)gr * DIM + k0 + kk]);
            }
            CP_COMMIT();
        }

        // ================= GEMM1: [128 x 256] @ [256 x 128] =================
        FragC acc[2][4];
#pragma unroll
        for (int mi = 0; mi < 2; mi++)
#pragma unroll
            for (int ni = 0; ni < 4; ni++) wmma::fill_fragment(acc[mi][ni], 0.0f);

        for (int c = 0; c < NCH; c++) {
            if (c + 3 < NCH) {
                const int k0 = (c + 3) * KC;
                const uint32_t xb = XBUF((c + 3) & 3);
#pragma unroll
                for (int i = 0; i < 2; i++) {
                    int e = t + i * NT;
                    int r = e >> 2, kk = (e & 3) * 4;
                    int gr = rowBase + r; if (gr >= nRows) gr = nRows - 1;
                    CP16(sb + xb + (r * 20 + kk) * 4, &X[(size_t)gr * DIM + k0 + kk]);
                }
            }
            CP_COMMIT();
            CP_WAIT(3);
            __syncthreads();

            float* XB = (float*)(smem + XBUF(c & 3));
#pragma unroll
            for (int ks = 0; ks < 2; ks++) {
                const int kb = ks * 8;
                FragA a[2];
                FragB b[4];
#pragma unroll
                for (int mi = 0; mi < 2; mi++)
                    wmma::load_matrix_sync(a[mi], XB + (wm * 32 + mi * 16) * 20 + kb, 20);
#pragma unroll
                for (int ni = 0; ni < 4; ni++)
                    wmma::load_matrix_sync(b[ni], W1S + (c * KC + kb) * 132 + wn * 64 + ni * 16, 132);
#pragma unroll
                for (int mi = 0; mi < 2; mi++)
#pragma unroll
                    for (int ni = 0; ni < 4; ni++)
                        wmma::mma_sync(acc[mi][ni], a[mi], b[ni], acc[mi][ni]);
            }
            __syncthreads();
        }

        // ========== epilogue: 4 phases of 32 H1-dims, GEMM2 accumulates ==========
        FragC acc2[2][2];
#pragma unroll
        for (int mi = 0; mi < 2; mi++)
#pragma unroll
            for (int ni = 0; ni < 2; ni++) wmma::fill_fragment(acc2[mi][ni], 0.0f);

#pragma unroll
        for (int p = 0; p < 4; p++) {
            // store this phase's acc cols -> H1q (warps owning cols 32p..32p+31)
            if (wn == (p >> 1)) {
                const int nb = (p & 1) * 2;
#pragma unroll
                for (int mi = 0; mi < 2; mi++)
#pragma unroll
                    for (int u = 0; u < 2; u++)
                        wmma::store_matrix_sync(H1 + (wm * 32 + mi * 16) * 36 + u * 16,
                                                acc[mi][nb + u], 36, wmma::mem_row_major);
            }
            __syncthreads();
            // bias + relu on H1q [128 x 32]
#pragma unroll
            for (int i = 0; i < 4; i++) {
                int e = t + i * NT;
                int r = e >> 3, cc = (e & 7) * 4;
                float4 v = *(float4*)&H1[r * 36 + cc];
                v.x = fmaxf(v.x + BIAS[p * 32 + cc + 0], 0.f);
                v.y = fmaxf(v.y + BIAS[p * 32 + cc + 1], 0.f);
                v.z = fmaxf(v.z + BIAS[p * 32 + cc + 2], 0.f);
                v.w = fmaxf(v.w + BIAS[p * 32 + cc + 3], 0.f);
                *(float4*)&H1[r * 36 + cc] = v;
            }
            __syncthreads();
            // GEMM2 partial: K rows 32p..32p+31 of W2
#pragma unroll
            for (int ks = 0; ks < 4; ks++) {
                const int kb = ks * 8;
                FragA a2[2];
                FragB b2[2];
#pragma unroll
                for (int mi = 0; mi < 2; mi++)
                    wmma::load_matrix_sync(a2[mi], H1 + (wm * 32 + mi * 16) * 36 + kb, 36);
#pragma unroll
                for (int ni = 0; ni < 2; ni++)
                    wmma::load_matrix_sync(b2[ni], W2S + (p * 32 + kb) * 68 + wn * 32 + ni * 16, 68);
#pragma unroll
                for (int mi = 0; mi < 2; mi++)
#pragma unroll
                    for (int ni = 0; ni < 2; ni++)
                        wmma::mma_sync(acc2[mi][ni], a2[mi], b2[ni], acc2[mi][ni]);
            }
            __syncthreads();
        }

        // ---- store D2 -> H2, layer 3 + exp + segment sum ----
#pragma unroll
        for (int mi = 0; mi < 2; mi++)
#pragma unroll
            for (int ni = 0; ni < 2; ni++)
                wmma::store_matrix_sync(H2 + (wm * 32 + mi * 16) * 68 + wn * 32 + ni * 16,
                                        acc2[mi][ni], 68, wmma::mem_row_major);
        __syncthreads();
        {
            const int row = t >> 1;        // 0..127
            const int q   = t & 1;         // 2 threads/row, 32 cols each
            float s = 0.0f;
#pragma unroll
            for (int j = 0; j < 32; j++) {
                int c = q * 32 + j;
                float v = fmaxf(H2[row * 68 + c] + BIAS[128 + c], 0.0f);
                s = fmaf(v, BIAS[192 + c], s);
            }
            s += __shfl_xor_sync(0xFFFFFFFF, s, 1);
            if (q == 0) {
                int gr = rowBase + row;
                if (gr < nRows) {
                    float e = __expf(s + b3v);   // logits O(1): no max-subtraction needed
                    g_ebuf[eOff + gr] = e;
                    atomicAdd(&g_segsum[sOff + idx[gr]], e);
                }
            }
        }
        __syncthreads();   // H2 (X region) free before next tile's cp.async
    }
}

// ---------------- pool: att-weighted segment sum (sorted indices) ----------------
__global__ void __launch_bounds__(NT)
pool_kernel(const float* __restrict__ Xn, const int* __restrict__ idxn,
            const float* __restrict__ Xe, const int* __restrict__ idxe,
            float* __restrict__ out, int nbNodes, int nNodes, int nEdges) {
    __shared__ float rw[PROWS];
    __shared__ int   sg[PROWS];

    const int bid = blockIdx.x;
    const bool isNode = bid < nbNodes;
    const float* X   = isNode ? Xn : Xe;
    const int*   idx = isNode ? idxn : idxe;
    const int nRows  = isNode ? nNodes : nEdges;
    const int eOff   = isNode ? 0 : 200000;
    const int sOff   = isNode ? 0 : NGRAPH;
    float* outH      = isNode ? out : out + NGRAPH * DIM;
    const int base   = (isNode ? bid : bid - nbNodes) * PROWS;
    const int rows   = min(PROWS, nRows - base);

    const int t = threadIdx.x;
    for (int i = t; i < rows; i += NT) {
        int g = base + i;
        int s = idx[g];
        sg[i] = s;
        rw[i] = g_ebuf[eOff + g] / g_segsum[sOff + s];
    }
    __syncthreads();

    const int grp = t >> 6;
    const int col = (t & 63) * 4;
    const int r0 = grp * 128;
    if (r0 < rows) {
        const int rend = min(r0 + 128, rows);
        float4 acc = make_float4(0.f, 0.f, 0.f, 0.f);
        int cur = sg[r0];
        for (int i = r0; i < rend; i++) {
            float4 x = *(const float4*)&X[(size_t)(base + i) * DIM + col];
            int s = sg[i];
            if (s != cur) {
                size_t o = (size_t)cur * DIM + col;
                atomicAdd(&outH[o + 0], acc.x);
                atomicAdd(&outH[o + 1], acc.y);
                atomicAdd(&outH[o + 2], acc.z);
                atomicAdd(&outH[o + 3], acc.w);
                acc = make_float4(0.f, 0.f, 0.f, 0.f);
                cur = s;
            }
            float w = rw[i];
            acc.x = fmaf(w, x.x, acc.x);
            acc.y = fmaf(w, x.y, acc.y);
            acc.z = fmaf(w, x.z, acc.z);
            acc.w = fmaf(w, x.w, acc.w);
        }
        size_t o = (size_t)cur * DIM + col;
        atomicAdd(&outH[o + 0], acc.x);
        atomicAdd(&outH[o + 1], acc.y);
        atomicAdd(&outH[o + 2], acc.z);
        atomicAdd(&outH[o + 3], acc.w);
    }
}

// ---------------- launch ----------------
extern "C" void kernel_launch(void* const* d_in, const int* in_sizes, int n_in,
                              void* d_out, int out_size) {
    const float* emb_nodes  = (const float*)d_in[0];
    const float* emb_edges  = (const float*)d_in[1];
    const int*   node_index = (const int*)d_in[2];
    const int*   edge_index = (const int*)d_in[3];
    const float* Wn1 = (const float*)d_in[4];
    const float* bn1 = (const float*)d_in[5];
    const float* Wn2 = (const float*)d_in[6];
    const float* bn2 = (const float*)d_in[7];
    const float* Wn3 = (const float*)d_in[8];
    const float* bn3 = (const float*)d_in[9];
    const float* We1 = (const float*)d_in[10];
    const float* be1 = (const float*)d_in[11];
    const float* We2 = (const float*)d_in[12];
    const float* be2 = (const float*)d_in[13];
    const float* We3 = (const float*)d_in[14];
    const float* be3 = (const float*)d_in[15];

    const int n_nodes = in_sizes[0] / DIM;   // 200000
    const int n_edges = in_sizes[1] / DIM;   // 400000
    float* out = (float*)d_out;

    init_kernel<<<(out_size + NT - 1) / NT, NT>>>(out, out_size);

    cudaFuncSetAttribute(mlp_kernel, cudaFuncAttributeMaxDynamicSharedMemorySize, SMEM_TOTAL);
    mlp_kernel<<<CTA_TOTAL, NT, SMEM_TOTAL>>>(
        emb_nodes, node_index, Wn1, bn1, Wn2, bn2, Wn3, bn3,
        emb_edges, edge_index, We1, be1, We2, be2, We3, be3,
        n_nodes, n_edges);

    const int pn = (n_nodes + PROWS - 1) / PROWS;
    const int pe = (n_edges + PROWS - 1) / PROWS;
    pool_kernel<<<pn + pe, NT>>>(
        emb_nodes, node_index, emb_edges, edge_index, out, pn, n_nodes, n_edges);
}